// round 11
// baseline (speedup 1.0000x reference)
#include <cuda_runtime.h>
#include <stdint.h>

// PointPillars BEV scatter: (M,3) coords + (M,64) features -> (B,64,496,432)
#define BEV_H   496
#define BEV_W   432
#define NB      4
#define NC      64
#define HW      (BEV_H * BEV_W)        // 214272 cells per batch image
#define NCELLS  (NB * HW)              // 857088 cells total
#define CPT     16                     // channels per thread
#define NCG     (NC / CPT)             // 4 channel groups
#define CELLS_PB 64                    // cells per block (block = 64*4 = 256 thr)
#define NBLK    (NCELLS / CELLS_PB)    // 13392 blocks, exact (HW % 64 == 0)

// Inverse map: raveled cell -> pillar index + 1 (0 = empty). 3.43 MB.
// Zero at module load; clear_idx_kernel re-zeroes exactly the occupied
// entries after each gather, so the map is all-zero again at end of call.
__device__ int g_map[NCELLS];

// ---------------------------------------------------------------------------
// Kernel 1: scatter pillar index+1 into the map (coords are collision-free).
__global__ void scatter_idx_kernel(const int* __restrict__ coords, int M) {
    int m = blockIdx.x * blockDim.x + threadIdx.x;
    if (m < M) {
        int b = coords[3 * m + 0];
        int y = coords[3 * m + 1];
        int x = coords[3 * m + 2];
        g_map[(b * BEV_H + y) * BEV_W + x] = m + 1;
    }
}

// ---------------------------------------------------------------------------
// Kernel 2: barrier-free dense gather. t>>6 -> channel group (16 ch),
// t&63 -> cell offset; each warp's 32 lanes are consecutive cells of one cg.
// Per thread:
//   1 scalar map LDG (coalesced 128B/warp),
//   4 float4 feature loads ONLY if occupied (~14% of lanes),
//   16 scalar streaming stores; each warp store instr = 128B contiguous.
// No __syncthreads, no map writeback -> pure flow-through.
__global__ __launch_bounds__(256, 6) void gather_kernel(
    const float* __restrict__ feat, float* __restrict__ out) {
    const int t    = threadIdx.x;
    const int cg   = t >> 6;                        // 0..3
    const int cell = blockIdx.x * CELLS_PB + (t & 63);

    const int pid = __ldg(&g_map[cell]);

    float4 v0 = make_float4(0.f, 0.f, 0.f, 0.f);
    float4 v1 = v0, v2 = v0, v3 = v0;
    if (pid) {
        const float4* fp = reinterpret_cast<const float4*>(
            feat + (size_t)(pid - 1) * NC + cg * CPT);
        v0 = fp[0]; v1 = fp[1]; v2 = fp[2]; v3 = fp[3];
    }

    const int b = cell / HW;                        // uniform per block
    float* outp = out + ((size_t)(b * NC + cg * CPT)) * HW + (cell - b * HW);
    const size_t cs = (size_t)HW;
    __stcs(outp, v0.x); outp += cs;
    __stcs(outp, v0.y); outp += cs;
    __stcs(outp, v0.z); outp += cs;
    __stcs(outp, v0.w); outp += cs;
    __stcs(outp, v1.x); outp += cs;
    __stcs(outp, v1.y); outp += cs;
    __stcs(outp, v1.z); outp += cs;
    __stcs(outp, v1.w); outp += cs;
    __stcs(outp, v2.x); outp += cs;
    __stcs(outp, v2.y); outp += cs;
    __stcs(outp, v2.z); outp += cs;
    __stcs(outp, v2.w); outp += cs;
    __stcs(outp, v3.x); outp += cs;
    __stcs(outp, v3.y); outp += cs;
    __stcs(outp, v3.z); outp += cs;
    __stcs(outp, v3.w);
}

// ---------------------------------------------------------------------------
// Kernel 3: re-zero exactly the occupied map entries (runs after gather).
__global__ void clear_idx_kernel(const int* __restrict__ coords, int M) {
    int m = blockIdx.x * blockDim.x + threadIdx.x;
    if (m < M) {
        int b = coords[3 * m + 0];
        int y = coords[3 * m + 1];
        int x = coords[3 * m + 2];
        g_map[(b * BEV_H + y) * BEV_W + x] = 0;
    }
}

// ---------------------------------------------------------------------------
extern "C" void kernel_launch(void* const* d_in, const int* in_sizes, int n_in,
                              void* d_out, int out_size) {
    const int*   coords = (const int*)d_in[0];    // (M, 3) int32
    const float* feat   = (const float*)d_in[1];  // (M, 64) float32
    float*       out    = (float*)d_out;          // (4, 64, 496, 432) float32
    const int M = in_sizes[0] / 3;

    scatter_idx_kernel<<<(M + 255) / 256, 256>>>(coords, M);
    gather_kernel<<<NBLK, 256>>>(feat, out);
    clear_idx_kernel<<<(M + 255) / 256, 256>>>(coords, M);
}